// round 8
// baseline (speedup 1.0000x reference)
#include <cuda_runtime.h>
#include <cuda_pipeline.h>
#include <math.h>
#include <stdint.h>

#define BB    32
#define TT    2048
#define DD    128
#define FF    16
#define SS    64
#define RR    64
#define STATE 1024
#define TWO_PI 6.28318530717958647692f

#define NWGEN 4096                 // M-generator CTAs (256 jgroups x 16 tgroups)
#define NCONS 1024                 // consumer CTAs (32 chunks x 32 jtiles)
#define CHK   64                   // steps per chunk

// ---------------- scratch (__device__ globals; no allocation allowed) -------
__device__ float g_U[TT * SS * RR];                    // 32 MB
__device__ float g_C[(TT + 1) * FF];                   // c_f(t), row 0 = 0
__device__ float g_W[(size_t)TT * SS * STATE];         // 512 MB  M_t[s][j]
__device__ float g_stats[(TT + 1) * SS * BB];          // 16.8 MB [t][s][b], row 0 = 0
__device__ float g_chk[33 * STATE * BB];               // 4.2 MB  [chunk][k][b]
__device__ int   g_done[33];                           // producer flags (idx 1..32)
__device__ int   g_wdone[16];                          // wgen flags per tgroup

__device__ __forceinline__ float gelu_exact(float v) { return v * normcdff(v); }

// ---------------------------------------------------------------------------
// Kernel A: precompute U_t and c_f(t); zero flags and t=0 rows
// ---------------------------------------------------------------------------
__global__ void precompute_U(const float* __restrict__ Wr,
                             const float* __restrict__ phases) {
    int t = blockIdx.x + 1;
    if (blockIdx.x == 0) {
        if (threadIdx.x < 33) g_done[threadIdx.x] = 0;
        if (threadIdx.x < 16) g_wdone[threadIdx.x] = 0;
        if (threadIdx.x < FF) g_C[threadIdx.x] = 0.f;
        for (int i = threadIdx.x; i < SS * BB; i += blockDim.x) g_stats[i] = 0.f;
    }
    __shared__ float c[FF];
    if (threadIdx.x < FF) {
        float f = (float)threadIdx.x;
        float ang = (TWO_PI / (float)TT) * (float)t * f + TWO_PI * phases[threadIdx.x];
        c[threadIdx.x] = cosf(ang) * (1.0f / (float)TT);
        g_C[t * FF + threadIdx.x] = c[threadIdx.x];
    }
    __syncthreads();
    float* Udst = g_U + (size_t)(t - 1) * (SS * RR);
    for (int idx = threadIdx.x; idx < SS * RR; idx += blockDim.x) {
        int s = idx >> 6, r = idx & 63;
        float acc = 0.f;
#pragma unroll
        for (int f = 0; f < FF; ++f)
            acc += c[f] * Wr[(f * SS + s) * RR + r];
        Udst[idx] = acc;
    }
}

// ---------------------------------------------------------------------------
// Fused kernel roles share one dynamic smem buffer (44 KB)
// ---------------------------------------------------------------------------
#define FUSED_SMEM (44 * 1024)

struct RecSmem {
    float sU[2][SS * RR];
    float sx[2][DD];
    float sstate[STATE];
    float sP[RR], sP0[RR], sstats[SS], srecur[RR];
    float sredA[256], sredB[256];
    float sc[FF], sph2[FF], sbr[RR], sbs[SS];
};

// ---------------------------------------------------------------------------
// Role 1: recurrence producer. One CTA per batch.
// ---------------------------------------------------------------------------
__device__ void recurrence_body(char* smraw,
                                const float* __restrict__ x,
                                const float* __restrict__ Ws,
                                const float* __restrict__ bs,
                                const float* __restrict__ br,
                                const float* __restrict__ Wr,
                                const float* __restrict__ phases) {
    RecSmem* sm = (RecSmem*)smraw;
    const int tid  = threadIdx.x;
    const int lane = tid & 63;
    const int grp  = tid >> 6;
    const int b    = blockIdx.x;

    float wsr[48];
#pragma unroll
    for (int kk = 0; kk < 48; ++kk)
        wsr[kk] = Ws[(grp * 48 + kk) * SS + lane];
    float wr0r[16];
#pragma unroll
    for (int ss = 0; ss < 16; ++ss)
        wr0r[ss] = Wr[(grp * 16 + ss) * RR + lane];

    for (int i = tid; i < STATE; i += 256) sm->sstate[i] = 0.f;
    if (tid < RR) { sm->sP[tid] = 0.f; sm->sP0[tid] = 0.f; sm->sbr[tid] = br[tid]; }
    if (tid < SS) { sm->sbs[tid] = bs[tid]; }
    if (tid < FF) { sm->sph2[tid] = TWO_PI * phases[tid]; }

    {
        const float* Usrc = g_U;
#pragma unroll
        for (int q = 0; q < 4; ++q) {
            int i = tid + q * 256;
            __pipeline_memcpy_async(&sm->sU[0][i * 4], &Usrc[i * 4], 16);
        }
        if (tid < 32)
            __pipeline_memcpy_async(&sm->sx[0][tid * 4],
                                    x + ((size_t)b * TT) * DD + tid * 4, 16);
        __pipeline_commit();
    }

    const float invL  = 1.0f / (float)TT;
    const float wbase = TWO_PI / (float)TT;

    for (int t = 1; t <= TT; ++t) {
        const int cur = (t - 1) & 1;
        const int nxt = cur ^ 1;

        __pipeline_wait_prior(0);
        __syncthreads();

        if (t < TT) {
            const float* Usrc = g_U + (size_t)t * (SS * RR);
#pragma unroll
            for (int q = 0; q < 4; ++q) {
                int i = tid + q * 256;
                __pipeline_memcpy_async(&sm->sU[nxt][i * 4], &Usrc[i * 4], 16);
            }
            if (tid < 32)
                __pipeline_memcpy_async(&sm->sx[nxt][tid * 4],
                                        x + ((size_t)b * TT + t) * DD + tid * 4, 16);
            __pipeline_commit();
        }

        if (tid < FF) {
            float fv = (float)tid;
            sm->sc[tid] = invL * cosf(wbase * (float)t * fv + sm->sph2[tid]);
        }
        if (tid < RR) {
            float v = sm->sP[tid] + sm->sbr[tid];
            sm->srecur[tid] = gelu_exact(v);
        }
        __syncthreads();

        {
            float a0 = 0.f, a1 = 0.f, a2 = 0.f, a3 = 0.f;
            const int k0 = grp * 48;
#pragma unroll
            for (int kk = 0; kk < 48; ++kk) {
                int k = k0 + kk;
                float v = (k < DD) ? sm->sx[cur][k] : sm->srecur[k - DD];
                float p = v * wsr[kk];
                if ((kk & 3) == 0) a0 += p;
                else if ((kk & 3) == 1) a1 += p;
                else if ((kk & 3) == 2) a2 += p;
                else a3 += p;
            }
            sm->sredA[grp * 64 + lane] = (a0 + a1) + (a2 + a3);
        }
        __syncthreads();

        if (tid < SS) {
            float v = sm->sredA[tid] + sm->sredA[64 + tid] + sm->sredA[128 + tid] +
                      sm->sredA[192 + tid] + sm->sbs[tid];
            float g = gelu_exact(v);
            sm->sstats[tid] = g;
            g_stats[(size_t)t * (SS * BB) + tid * BB + b] = g;   // [t][s][b]
        }
        __syncthreads();

        {
#pragma unroll
            for (int q = 0; q < 4; ++q) {
                int i = tid + q * 256;
                int f = i >> 6, s = i & 63;
                float prev = (f == 0) ? 0.f : sm->sstate[i];
                float ns = prev + sm->sc[f] * sm->sstats[s];
                sm->sstate[i] = ns;
                if ((t & (CHK - 1)) == 0)
                    g_chk[(size_t)(t >> 6) * (STATE * BB) + i * BB + b] = ns;
            }
        }

        {
            float a1 = 0.f, b1 = 0.f, a2 = 0.f, b2 = 0.f;
            const int s0 = grp * 16;
#pragma unroll
            for (int ss = 0; ss < 16; ++ss) {
                float sv = sm->sstats[s0 + ss];
                float u  = sm->sU[cur][(s0 + ss) * RR + lane];
                if (ss & 1) { a1 += sv * u; b1 += sv * wr0r[ss]; }
                else        { a2 += sv * u; b2 += sv * wr0r[ss]; }
            }
            sm->sredA[grp * 64 + lane] = a1 + a2;
            sm->sredB[grp * 64 + lane] = b1 + b2;
        }
        __syncthreads();

        if (tid < RR) {
            float su = sm->sredA[tid] + sm->sredA[64 + tid] + sm->sredA[128 + tid] + sm->sredA[192 + tid];
            float sw = sm->sredB[tid] + sm->sredB[64 + tid] + sm->sredB[128 + tid] + sm->sredB[192 + tid];
            float np = sm->sP[tid] - sm->sP0[tid] + su;
            sm->sP[tid]  = np;
            sm->sP0[tid] = sm->sc[0] * sw;
        }
        if ((t & (CHK - 1)) == 0 && tid == 128) {
            __threadfence();
            atomicAdd(&g_done[t >> 6], 1);
        }
    }
}

// ---------------------------------------------------------------------------
// Role 2: M_t generator. M_t[s][j] = sum_{f>=1} c_f(t) * Wo[f*64+s][j].
// CTA = 64 s x 4 j, covers 128 t values.
// ---------------------------------------------------------------------------
__device__ void wgen_body(char* smraw, const float* __restrict__ Wo) {
    float* sc2 = (float*)smraw;   // 128 t x 16 f = 8 KB
    const int tid = threadIdx.x;
    const int wi  = blockIdx.x - BB;
    const int jg  = wi & 255;
    const int tg  = wi >> 8;
    const int j   = (jg << 2) + (tid & 3);
    const int s   = tid >> 2;

    float wo[FF - 1];
#pragma unroll
    for (int f = 1; f < FF; ++f)
        wo[f - 1] = Wo[(size_t)(f * SS + s) * STATE + j];

    const float* csrc = g_C + (size_t)(tg * 128 + 1) * FF;
    for (int i = tid; i < 128 * FF; i += 256) sc2[i] = csrc[i];
    __syncthreads();

    size_t base = (size_t)(tg * 128) * (SS * STATE) + (size_t)s * STATE + j;
    for (int tt = 0; tt < 128; ++tt) {
        float acc = 0.f;
#pragma unroll
        for (int f = 1; f < FF; ++f)
            acc += sc2[tt * FF + f] * wo[f - 1];
        g_W[base + (size_t)tt * (SS * STATE)] = acc;
    }
    __syncthreads();
    if (tid == 0) { __threadfence(); atomicAdd(&g_wdone[tg], 1); }
}

// ---------------------------------------------------------------------------
// Role 3: consumer. CTA = (chunk c, jtile of 32). Thread owns (b, 4 j).
//   G_t += stats_t @ M_t ;  out_t = gelu(G_t + c0(t)*(stats_t @ Wo_0) + bo)
// ---------------------------------------------------------------------------
#define OFF_WO0 0
#define OFF_W   8192
#define OFF_S   24576
#define OFF_B   40960

__device__ void consumer_body(char* smraw,
                              const float* __restrict__ Wo,
                              const float* __restrict__ bo,
                              float* __restrict__ out) {
    float* sWo0  = (float*)(smraw + OFF_WO0);   // [64][32]
    float* sW    = (float*)(smraw + OFF_W);     // [2][64][32]
    float* sS    = (float*)(smraw + OFF_S);     // [2][64][32]
    float* sbias = (float*)(smraw + OFF_B);     // [32]

    const int tid = threadIdx.x;
    const int ci  = blockIdx.x - (BB + NWGEN);
    const int c   = ci >> 5;                    // chunk 0..31
    const int j0  = (ci & 31) << 5;             // 0..992
    const int b   = tid >> 3;                   // 0..31
    const int jj  = (tid & 7) << 2;             // 0,4,..,28

    if (tid == 0) {
        while (*(volatile int*)&g_wdone[c >> 1] < 256) __nanosleep(512);
        while (*(volatile int*)&g_done[c + 1] < BB)    __nanosleep(512);
        __threadfence();
    }
    __syncthreads();

    for (int i = tid; i < SS * 32; i += 256) {
        int s = i >> 5, jc = i & 31;
        sWo0[i] = Wo[(size_t)s * STATE + j0 + jc];
    }
    if (tid < 32) sbias[tid] = bo[j0 + tid];

    float G[4] = {0.f, 0.f, 0.f, 0.f};

    // --- rebuild G at chunk start from checkpoint (rows 64..1023 of Wo) ----
    if (c > 0) {
        const float* chkp = g_chk + (size_t)c * (STATE * BB);
#define PF_CHK(kt, buf) do {                                                   \
    const float* s1 = chkp + (size_t)(kt) * (64 * BB);                         \
    _Pragma("unroll")                                                          \
    for (int q = 0; q < 2; ++q) {                                              \
        int i = tid + q * 256;                                                 \
        __pipeline_memcpy_async(sS + (buf) * 2048 + i * 4, s1 + i * 4, 16);    \
        int k = i >> 3, part = (i & 7) << 2;                                   \
        __pipeline_memcpy_async(sW + (buf) * 2048 + k * 32 + part,             \
            Wo + (size_t)((kt) * 64 + k) * STATE + j0 + part, 16);             \
    }                                                                          \
    __pipeline_commit();                                                       \
} while (0)
        PF_CHK(1, 0);
        for (int kt = 1; kt < 16; ++kt) {
            const int cur = (kt - 1) & 1;
            __pipeline_wait_prior(0);
            __syncthreads();
            if (kt < 15) PF_CHK(kt + 1, cur ^ 1);
            const float* cs = sS + cur * 2048;
            const float* ws = sW + cur * 2048;
#pragma unroll 8
            for (int k = 0; k < 64; ++k) {
                float sv = cs[k * 32 + b];
                float4 w4 = *(const float4*)&ws[k * 32 + jj];
                G[0] += sv * w4.x; G[1] += sv * w4.y;
                G[2] += sv * w4.z; G[3] += sv * w4.w;
            }
            __syncthreads();
        }
#undef PF_CHK
    }

    // --- main incremental loop over 64 steps --------------------------------
    const int t0 = c << 6;
#define PF_T(t, buf) do {                                                      \
    const float* wsrc = g_W + (size_t)((t) - 1) * (SS * STATE) + j0;           \
    const float* ssrc = g_stats + (size_t)(t) * (SS * BB);                     \
    _Pragma("unroll")                                                          \
    for (int q = 0; q < 2; ++q) {                                              \
        int i = tid + q * 256;                                                 \
        __pipeline_memcpy_async(sS + (buf) * 2048 + i * 4, ssrc + i * 4, 16);  \
        int s = i >> 3, part = (i & 7) << 2;                                   \
        __pipeline_memcpy_async(sW + (buf) * 2048 + s * 32 + part,             \
                                wsrc + (size_t)s * STATE + part, 16);          \
    }                                                                          \
    __pipeline_commit();                                                       \
} while (0)

    PF_T(t0 + 1, 0);
    for (int tt = 0; tt < CHK; ++tt) {
        const int t = t0 + 1 + tt;
        const int cur = tt & 1;
        __pipeline_wait_prior(0);
        __syncthreads();
        if (tt < CHK - 1) PF_T(t + 1, cur ^ 1);

        const float* cs = sS + cur * 2048;
        const float* ws = sW + cur * 2048;
        float v[4] = {0.f, 0.f, 0.f, 0.f};
        float qc[4] = {0.f, 0.f, 0.f, 0.f};
#pragma unroll 4
        for (int k = 0; k < 64; ++k) {
            float sv = cs[k * 32 + b];
            float4 w4 = *(const float4*)&ws[k * 32 + jj];
            float4 w0 = *(const float4*)&sWo0[k * 32 + jj];
            v[0] += sv * w4.x; v[1] += sv * w4.y;
            v[2] += sv * w4.z; v[3] += sv * w4.w;
            qc[0] += sv * w0.x; qc[1] += sv * w0.y;
            qc[2] += sv * w0.z; qc[3] += sv * w0.w;
        }
        const float c0 = __ldg(&g_C[t * FF]);
        G[0] += v[0]; G[1] += v[1]; G[2] += v[2]; G[3] += v[3];
        float4 o;
        o.x = gelu_exact(G[0] + c0 * qc[0] + sbias[jj + 0]);
        o.y = gelu_exact(G[1] + c0 * qc[1] + sbias[jj + 1]);
        o.z = gelu_exact(G[2] + c0 * qc[2] + sbias[jj + 2]);
        o.w = gelu_exact(G[3] + c0 * qc[3] + sbias[jj + 3]);
        *(float4*)(out + ((size_t)b * TT + (t - 1)) * STATE + j0 + jj) = o;
    }
#undef PF_T
}

// ---------------------------------------------------------------------------
__global__ __launch_bounds__(256, 2)
void fru_fused(const float* __restrict__ x,
               const float* __restrict__ Ws,
               const float* __restrict__ bs,
               const float* __restrict__ br,
               const float* __restrict__ Wr,
               const float* __restrict__ phases,
               const float* __restrict__ Wo,
               const float* __restrict__ bo,
               float* __restrict__ out) {
    extern __shared__ __align__(128) char smraw[];
    if (blockIdx.x < BB)
        recurrence_body(smraw, x, Ws, bs, br, Wr, phases);
    else if (blockIdx.x < BB + NWGEN)
        wgen_body(smraw, Wo);
    else
        consumer_body(smraw, Wo, bo, out);
}

// ---------------------------------------------------------------------------
extern "C" void kernel_launch(void* const* d_in, const int* in_sizes, int n_in,
                              void* d_out, int out_size) {
    const float* x   = (const float*)d_in[0];  // (B,T,D)
    const float* Wr  = (const float*)d_in[1];  // (STATE,R)
    const float* br  = (const float*)d_in[2];  // (R,)
    const float* Ws  = (const float*)d_in[3];  // (D+R,S)
    const float* bs  = (const float*)d_in[4];  // (S,)
    const float* Wo  = (const float*)d_in[5];  // (STATE,STATE)
    const float* bo  = (const float*)d_in[6];  // (STATE,)
    const float* ph  = (const float*)d_in[7];  // (1,F,1)
    float* out = (float*)d_out;

    cudaFuncSetAttribute(fru_fused, cudaFuncAttributeMaxDynamicSharedMemorySize, FUSED_SMEM);

    precompute_U<<<TT, 256>>>(Wr, ph);
    fru_fused<<<BB + NWGEN + NCONS, 256, FUSED_SMEM>>>(
        x, Ws, bs, br, Wr, ph, Wo, bo, out);
}

// round 11
// speedup vs baseline: 1.1003x; 1.1003x over previous
#include <cuda_runtime.h>
#include <cuda_pipeline.h>
#include <math.h>
#include <stdint.h>

#define BB    32
#define TT    2048
#define DD    128
#define FF    16
#define SS    64
#define RR    64
#define STATE 1024
#define TWO_PI 6.28318530717958647692f

#define CHK    32                  // steps per chunk
#define NCHUNK (TT / CHK)          // 64
#define JT     128                 // j columns per consumer tile
#define NJT    (STATE / JT)        // 8
#define NCONS  (NCHUNK * NJT)      // 512

// ---------------- scratch (__device__ globals; no allocation allowed) -------
__device__ float g_U[TT * SS * RR];                        // 32 MB
__device__ float g_C[(TT + 1) * FF];                       // c_f(t)
__device__ float g_W[(size_t)NCONS * CHK * SS * JT];       // 512 MB, per-consumer slices
__device__ float g_stats[(TT + 1) * SS * BB];              // [t][s][b]
__device__ float g_chk[(NCHUNK + 1) * STATE * BB];         // [chunk][k][b]
__device__ int   g_done[NCHUNK + 1];                       // producer flags

__device__ __forceinline__ float gelu_exact(float v) { return v * normcdff(v); }

// ---------------------------------------------------------------------------
// Kernel A: precompute U_t and c_f(t); zero flags
// ---------------------------------------------------------------------------
__global__ void precompute_U(const float* __restrict__ Wr,
                             const float* __restrict__ phases) {
    int t = blockIdx.x + 1;
    if (blockIdx.x == 0) {
        if (threadIdx.x < NCHUNK + 1) g_done[threadIdx.x] = 0;
        if (threadIdx.x < FF) g_C[threadIdx.x] = 0.f;
    }
    __shared__ float c[FF];
    if (threadIdx.x < FF) {
        float f = (float)threadIdx.x;
        float ang = (TWO_PI / (float)TT) * (float)t * f + TWO_PI * phases[threadIdx.x];
        c[threadIdx.x] = cosf(ang) * (1.0f / (float)TT);
        g_C[t * FF + threadIdx.x] = c[threadIdx.x];
    }
    __syncthreads();
    float* Udst = g_U + (size_t)(t - 1) * (SS * RR);
    for (int idx = threadIdx.x; idx < SS * RR; idx += blockDim.x) {
        int s = idx >> 6, r = idx & 63;
        float acc = 0.f;
#pragma unroll
        for (int f = 0; f < FF; ++f)
            acc += c[f] * Wr[(f * SS + s) * RR + r];
        Udst[idx] = acc;
    }
}

// ---------------------------------------------------------------------------
// Fused smem: consumer layout (floats):
//   [0, 8192)      sWo0  (also sc2 coeff buffer during generation)
//   [8192, 24576)  sW double buffer  2 x (64 x 128)
//   [24576, 28672) sS double buffer  2 x (64 x 32)
// = 114688 bytes. Producer RecSmem (~42 KB) overlays the same region.
// ---------------------------------------------------------------------------
#define FUSED_SMEM 114688

struct RecSmem {
    float sU[2][SS * RR];
    float sx[2][DD];
    float sstate[STATE];
    float sP[RR], sP0[RR], sstats[SS], srecur[RR];
    float sredA[256], sredB[256];
    float sc[FF], sph2[FF], sbr[RR], sbs[SS];
};

// ---------------------------------------------------------------------------
// Role 1: recurrence producer (unchanged math; checkpoints every CHK steps)
// ---------------------------------------------------------------------------
__device__ void recurrence_body(char* smraw,
                                const float* __restrict__ x,
                                const float* __restrict__ Ws,
                                const float* __restrict__ bs,
                                const float* __restrict__ br,
                                const float* __restrict__ Wr,
                                const float* __restrict__ phases) {
    RecSmem* sm = (RecSmem*)smraw;
    const int tid  = threadIdx.x;
    const int lane = tid & 63;
    const int grp  = tid >> 6;
    const int b    = blockIdx.x;

    float wsr[48];
#pragma unroll
    for (int kk = 0; kk < 48; ++kk)
        wsr[kk] = Ws[(grp * 48 + kk) * SS + lane];
    float wr0r[16];
#pragma unroll
    for (int ss = 0; ss < 16; ++ss)
        wr0r[ss] = Wr[(grp * 16 + ss) * RR + lane];

    for (int i = tid; i < STATE; i += 256) sm->sstate[i] = 0.f;
    if (tid < RR) { sm->sP[tid] = 0.f; sm->sP0[tid] = 0.f; sm->sbr[tid] = br[tid]; }
    if (tid < SS) { sm->sbs[tid] = bs[tid]; }
    if (tid < FF) { sm->sph2[tid] = TWO_PI * phases[tid]; }

    {
        const float* Usrc = g_U;
#pragma unroll
        for (int q = 0; q < 4; ++q) {
            int i = tid + q * 256;
            __pipeline_memcpy_async(&sm->sU[0][i * 4], &Usrc[i * 4], 16);
        }
        if (tid < 32)
            __pipeline_memcpy_async(&sm->sx[0][tid * 4],
                                    x + ((size_t)b * TT) * DD + tid * 4, 16);
        __pipeline_commit();
    }

    const float invL  = 1.0f / (float)TT;
    const float wbase = TWO_PI / (float)TT;

    for (int t = 1; t <= TT; ++t) {
        const int cur = (t - 1) & 1;
        const int nxt = cur ^ 1;

        __pipeline_wait_prior(0);
        __syncthreads();

        if (t < TT) {
            const float* Usrc = g_U + (size_t)t * (SS * RR);
#pragma unroll
            for (int q = 0; q < 4; ++q) {
                int i = tid + q * 256;
                __pipeline_memcpy_async(&sm->sU[nxt][i * 4], &Usrc[i * 4], 16);
            }
            if (tid < 32)
                __pipeline_memcpy_async(&sm->sx[nxt][tid * 4],
                                        x + ((size_t)b * TT + t) * DD + tid * 4, 16);
            __pipeline_commit();
        }

        if (tid < FF) {
            float fv = (float)tid;
            sm->sc[tid] = invL * cosf(wbase * (float)t * fv + sm->sph2[tid]);
        }
        if (tid < RR) {
            float v = sm->sP[tid] + sm->sbr[tid];
            sm->srecur[tid] = gelu_exact(v);
        }
        __syncthreads();

        {
            float a0 = 0.f, a1 = 0.f, a2 = 0.f, a3 = 0.f;
            const int k0 = grp * 48;
#pragma unroll
            for (int kk = 0; kk < 48; ++kk) {
                int k = k0 + kk;
                float v = (k < DD) ? sm->sx[cur][k] : sm->srecur[k - DD];
                float p = v * wsr[kk];
                if ((kk & 3) == 0) a0 += p;
                else if ((kk & 3) == 1) a1 += p;
                else if ((kk & 3) == 2) a2 += p;
                else a3 += p;
            }
            sm->sredA[grp * 64 + lane] = (a0 + a1) + (a2 + a3);
        }
        __syncthreads();

        if (tid < SS) {
            float v = sm->sredA[tid] + sm->sredA[64 + tid] + sm->sredA[128 + tid] +
                      sm->sredA[192 + tid] + sm->sbs[tid];
            float g = gelu_exact(v);
            sm->sstats[tid] = g;
            g_stats[(size_t)t * (SS * BB) + tid * BB + b] = g;   // [t][s][b]
        }
        __syncthreads();

        {
#pragma unroll
            for (int q = 0; q < 4; ++q) {
                int i = tid + q * 256;
                int f = i >> 6, s = i & 63;
                float prev = (f == 0) ? 0.f : sm->sstate[i];
                float ns = prev + sm->sc[f] * sm->sstats[s];
                sm->sstate[i] = ns;
                if ((t & (CHK - 1)) == 0)
                    g_chk[(size_t)(t / CHK) * (STATE * BB) + i * BB + b] = ns;
            }
        }

        {
            float a1 = 0.f, b1 = 0.f, a2 = 0.f, b2 = 0.f;
            const int s0 = grp * 16;
#pragma unroll
            for (int ss = 0; ss < 16; ++ss) {
                float sv = sm->sstats[s0 + ss];
                float u  = sm->sU[cur][(s0 + ss) * RR + lane];
                if (ss & 1) { a1 += sv * u; b1 += sv * wr0r[ss]; }
                else        { a2 += sv * u; b2 += sv * wr0r[ss]; }
            }
            sm->sredA[grp * 64 + lane] = a1 + a2;
            sm->sredB[grp * 64 + lane] = b1 + b2;
        }
        __syncthreads();

        if (tid < RR) {
            float su = sm->sredA[tid] + sm->sredA[64 + tid] + sm->sredA[128 + tid] + sm->sredA[192 + tid];
            float sw = sm->sredB[tid] + sm->sredB[64 + tid] + sm->sredB[128 + tid] + sm->sredB[192 + tid];
            float np = sm->sP[tid] - sm->sP0[tid] + su;
            sm->sP[tid]  = np;
            sm->sP0[tid] = sm->sc[0] * sw;
        }
        if ((t & (CHK - 1)) == 0 && tid == 128) {
            __threadfence();
            atomicAdd(&g_done[t / CHK], 1);
        }
    }
}

// ---------------------------------------------------------------------------
// Role 2: consumer. CTA = (chunk c, jtile j0 of 128).
//   Phase 1 (no wait): generate M_t slice into g_W (register-cached Wo rows).
//   Phase 2 (wait g_done[c]): rebuild G from checkpoint (rows 64..1023).
//   Phase 3 (wait g_done[c+1]): 32 incremental steps, write output.
// Thread tile 4b x 4j; warp = 4 jg x 8 bg (broadcast-friendly).
// ---------------------------------------------------------------------------
__device__ void consumer_body(char* smraw,
                              const float* __restrict__ Wo,
                              const float* __restrict__ bo,
                              float* __restrict__ out) {
    float* sWo0 = (float*)smraw;              // 8192 floats (also sc2)
    float* sW   = (float*)smraw + 8192;       // 2 x 8192
    float* sS   = (float*)smraw + 24576;      // 2 x 2048

    const int tid = threadIdx.x;
    const int ci  = (int)blockIdx.x - BB;
    const int c   = ci >> 3;                  // chunk 0..63
    const int j0  = (ci & 7) * JT;            // 0..896
    const int jg  = tid >> 3;                 // 0..31
    const int bg  = tid & 7;                  // 0..7
    const int jj  = jg * 4;
    const int b4  = bg * 4;

    // ---------------- Phase 1: generate M slice (no dependency) ------------
    {
        float* sc2 = sWo0;                    // overlay
        for (int i = tid; i < CHK * FF; i += 256)
            sc2[i] = g_C[(c * CHK + 1) * FF + i];
        __syncthreads();
        float* wslice = g_W + (size_t)ci * (CHK * SS * JT);
        for (int q = 0; q < 32; ++q) {
            int p = q * 256 + tid;            // 0..8191 : s = p>>7, j = p&127
            int s = p >> 7, j = p & 127;
            float wo[FF - 1];
#pragma unroll
            for (int f = 0; f < FF - 1; ++f)
                wo[f] = Wo[(size_t)((f + 1) * SS + s) * STATE + j0 + j];
#pragma unroll 4
            for (int tt = 0; tt < CHK; ++tt) {
                float acc = 0.f;
#pragma unroll
                for (int f = 0; f < FF - 1; ++f)
                    acc += sc2[tt * FF + f + 1] * wo[f];
                wslice[(size_t)tt * (SS * JT) + p] = acc;
            }
        }
        __syncthreads();                      // done with sc2 overlay
    }

    // Stage Wo0 (rows 0..63) into sWo0
    for (int q = 0; q < 8; ++q) {
        int i = q * 256 + tid;                // 16B units, 0..2047
        int k = i >> 5, seg = i & 31;
        __pipeline_memcpy_async(sWo0 + i * 4,
                                Wo + (size_t)k * STATE + j0 + seg * 4, 16);
    }
    __pipeline_commit();

    const float bo0 = bo[j0 + jj], bo1 = bo[j0 + jj + 1];
    const float bo2 = bo[j0 + jj + 2], bo3 = bo[j0 + jj + 3];

    float G[16];
#pragma unroll
    for (int i = 0; i < 16; ++i) G[i] = 0.f;

    // ---------------- Phase 2: rebuild from checkpoint ---------------------
    if (c > 0) {
        if (tid == 0) {
            while (*(volatile int*)&g_done[c] < BB) __nanosleep(512);
            __threadfence();
        }
        __syncthreads();
        const float* chkp = g_chk + (size_t)c * (STATE * BB);
#define PF_R(kt, buf) do {                                                     \
    for (int q = 0; q < 8; ++q) {                                              \
        int i = q * 256 + tid;                                                 \
        int k = i >> 5, seg = i & 31;                                          \
        __pipeline_memcpy_async(sW + (buf) * 8192 + i * 4,                     \
            Wo + (size_t)((kt) * 64 + k) * STATE + j0 + seg * 4, 16);          \
    }                                                                          \
    for (int q = 0; q < 2; ++q) {                                              \
        int i = q * 256 + tid;                                                 \
        __pipeline_memcpy_async(sS + (buf) * 2048 + i * 4,                     \
            chkp + (size_t)(kt) * 64 * BB + i * 4, 16);                        \
    }                                                                          \
    __pipeline_commit();                                                       \
} while (0)
        PF_R(1, 0);
        for (int kt = 1; kt < 16; ++kt) {
            const int buf = (kt - 1) & 1;
            __pipeline_wait_prior(0);
            __syncthreads();
            if (kt < 15) PF_R(kt + 1, buf ^ 1);
            const float* ws = sW + buf * 8192;
            const float* cs = sS + buf * 2048;
#pragma unroll 8
            for (int k = 0; k < 64; ++k) {
                float4 sv = *(const float4*)&cs[k * 32 + b4];
                float4 wv = *(const float4*)&ws[k * 128 + jj];
                G[0]  += sv.x * wv.x; G[1]  += sv.x * wv.y; G[2]  += sv.x * wv.z; G[3]  += sv.x * wv.w;
                G[4]  += sv.y * wv.x; G[5]  += sv.y * wv.y; G[6]  += sv.y * wv.z; G[7]  += sv.y * wv.w;
                G[8]  += sv.z * wv.x; G[9]  += sv.z * wv.y; G[10] += sv.z * wv.z; G[11] += sv.z * wv.w;
                G[12] += sv.w * wv.x; G[13] += sv.w * wv.y; G[14] += sv.w * wv.z; G[15] += sv.w * wv.w;
            }
            __syncthreads();
        }
#undef PF_R
    }

    // ---------------- Phase 3: incremental 32 steps -------------------------
    if (tid == 0) {
        while (*(volatile int*)&g_done[c + 1] < BB) __nanosleep(512);
        __threadfence();
    }
    __syncthreads();

    const float* wslice = g_W + (size_t)ci * (CHK * SS * JT);
#define PF_M(tt, buf) do {                                                     \
    for (int q = 0; q < 8; ++q) {                                              \
        int i = q * 256 + tid;                                                 \
        __pipeline_memcpy_async(sW + (buf) * 8192 + i * 4,                     \
            wslice + (size_t)(tt) * (SS * JT) + i * 4, 16);                    \
    }                                                                          \
    for (int q = 0; q < 2; ++q) {                                              \
        int i = q * 256 + tid;                                                 \
        __pipeline_memcpy_async(sS + (buf) * 2048 + i * 4,                     \
            g_stats + (size_t)(c * CHK + 1 + (tt)) * (SS * BB) + i * 4, 16);   \
    }                                                                          \
    __pipeline_commit();                                                       \
} while (0)

    PF_M(0, 0);
    for (int tt = 0; tt < CHK; ++tt) {
        const int t = c * CHK + 1 + tt;
        const int buf = tt & 1;
        __pipeline_wait_prior(0);
        __syncthreads();
        if (tt < CHK - 1) PF_M(tt + 1, buf ^ 1);

        const float* ws = sW + buf * 8192;
        const float* cs = sS + buf * 2048;
        float v[16], qc[16];
#pragma unroll
        for (int i = 0; i < 16; ++i) { v[i] = 0.f; qc[i] = 0.f; }
#pragma unroll 8
        for (int k = 0; k < 64; ++k) {
            float4 sv = *(const float4*)&cs[k * 32 + b4];
            float4 wv = *(const float4*)&ws[k * 128 + jj];
            float4 w0 = *(const float4*)&sWo0[k * 128 + jj];
            v[0]  += sv.x * wv.x; v[1]  += sv.x * wv.y; v[2]  += sv.x * wv.z; v[3]  += sv.x * wv.w;
            v[4]  += sv.y * wv.x; v[5]  += sv.y * wv.y; v[6]  += sv.y * wv.z; v[7]  += sv.y * wv.w;
            v[8]  += sv.z * wv.x; v[9]  += sv.z * wv.y; v[10] += sv.z * wv.z; v[11] += sv.z * wv.w;
            v[12] += sv.w * wv.x; v[13] += sv.w * wv.y; v[14] += sv.w * wv.z; v[15] += sv.w * wv.w;
            qc[0]  += sv.x * w0.x; qc[1]  += sv.x * w0.y; qc[2]  += sv.x * w0.z; qc[3]  += sv.x * w0.w;
            qc[4]  += sv.y * w0.x; qc[5]  += sv.y * w0.y; qc[6]  += sv.y * w0.z; qc[7]  += sv.y * w0.w;
            qc[8]  += sv.z * w0.x; qc[9]  += sv.z * w0.y; qc[10] += sv.z * w0.z; qc[11] += sv.z * w0.w;
            qc[12] += sv.w * w0.x; qc[13] += sv.w * w0.y; qc[14] += sv.w * w0.z; qc[15] += sv.w * w0.w;
        }
        const float c0 = __ldg(&g_C[t * FF]);
#pragma unroll
        for (int i = 0; i < 16; ++i) G[i] += v[i];
#pragma unroll
        for (int i = 0; i < 4; ++i) {
            float4 o;
            o.x = gelu_exact(G[i * 4 + 0] + c0 * qc[i * 4 + 0] + bo0);
            o.y = gelu_exact(G[i * 4 + 1] + c0 * qc[i * 4 + 1] + bo1);
            o.z = gelu_exact(G[i * 4 + 2] + c0 * qc[i * 4 + 2] + bo2);
            o.w = gelu_exact(G[i * 4 + 3] + c0 * qc[i * 4 + 3] + bo3);
            *(float4*)(out + ((size_t)(b4 + i) * TT + (t - 1)) * STATE + j0 + jj) = o;
        }
    }
#undef PF_M
}

// ---------------------------------------------------------------------------
__global__ __launch_bounds__(256, 2)
void fru_fused(const float* __restrict__ x,
               const float* __restrict__ Ws,
               const float* __restrict__ bs,
               const float* __restrict__ br,
               const float* __restrict__ Wr,
               const float* __restrict__ phases,
               const float* __restrict__ Wo,
               const float* __restrict__ bo,
               float* __restrict__ out) {
    extern __shared__ __align__(128) char smraw[];
    if (blockIdx.x < BB)
        recurrence_body(smraw, x, Ws, bs, br, Wr, phases);
    else
        consumer_body(smraw, Wo, bo, out);
}

// ---------------------------------------------------------------------------
extern "C" void kernel_launch(void* const* d_in, const int* in_sizes, int n_in,
                              void* d_out, int out_size) {
    const float* x   = (const float*)d_in[0];  // (B,T,D)
    const float* Wr  = (const float*)d_in[1];  // (STATE,R)
    const float* br  = (const float*)d_in[2];  // (R,)
    const float* Ws  = (const float*)d_in[3];  // (D+R,S)
    const float* bs  = (const float*)d_in[4];  // (S,)
    const float* Wo  = (const float*)d_in[5];  // (STATE,STATE)
    const float* bo  = (const float*)d_in[6];  // (STATE,)
    const float* ph  = (const float*)d_in[7];  // (1,F,1)
    float* out = (float*)d_out;

    cudaFuncSetAttribute(fru_fused, cudaFuncAttributeMaxDynamicSharedMemorySize, FUSED_SMEM);

    precompute_U<<<TT, 256>>>(Wr, ph);
    fru_fused<<<BB + NCONS, 256, FUSED_SMEM>>>(x, Ws, bs, br, Wr, ph, Wo, bo, out);
}

// round 16
// speedup vs baseline: 1.2421x; 1.1289x over previous
#include <cuda_runtime.h>
#include <cuda_pipeline.h>
#include <math.h>
#include <stdint.h>

#define BB    32
#define TT    2048
#define DD    128
#define FF    16
#define SS    64
#define RR    64
#define STATE 1024
#define TWO_PI 6.28318530717958647692f

#define CHK    32                  // steps per chunk
#define NCHUNK (TT / CHK)          // 64
#define JT     128                 // j columns per consumer tile
#define NJT    (STATE / JT)        // 8
#define NCONS  (NCHUNK * NJT)      // 512

// ---------------- scratch (__device__ globals; no allocation allowed) -------
__device__ float g_U[TT * SS * RR];                        // 32 MB
__device__ float g_C[(TT + 1) * FF];                       // c_f(t)
__device__ float g_W[(size_t)NCONS * CHK * SS * JT];       // 512 MB, per-consumer slices
__device__ float g_stats[(TT + 1) * SS * BB];              // [t][s][b]
__device__ float g_chk[(NCHUNK + 1) * STATE * BB];         // [chunk][k][b]
__device__ int   g_done[NCHUNK + 1];                       // producer flags

__device__ __forceinline__ float gelu_exact(float v) { return v * normcdff(v); }

// ---------------------------------------------------------------------------
// Kernel A: precompute U_t and c_f(t); zero flags
// ---------------------------------------------------------------------------
__global__ void precompute_U(const float* __restrict__ Wr,
                             const float* __restrict__ phases) {
    int t = blockIdx.x + 1;
    if (blockIdx.x == 0) {
        if (threadIdx.x < NCHUNK + 1) g_done[threadIdx.x] = 0;
        if (threadIdx.x < FF) g_C[threadIdx.x] = 0.f;
    }
    __shared__ float c[FF];
    if (threadIdx.x < FF) {
        float f = (float)threadIdx.x;
        float ang = (TWO_PI / (float)TT) * (float)t * f + TWO_PI * phases[threadIdx.x];
        c[threadIdx.x] = cosf(ang) * (1.0f / (float)TT);
        g_C[t * FF + threadIdx.x] = c[threadIdx.x];
    }
    __syncthreads();
    float* Udst = g_U + (size_t)(t - 1) * (SS * RR);
    for (int idx = threadIdx.x; idx < SS * RR; idx += blockDim.x) {
        int s = idx >> 6, r = idx & 63;
        float acc = 0.f;
#pragma unroll
        for (int f = 0; f < FF; ++f)
            acc += c[f] * Wr[(f * SS + s) * RR + r];
        Udst[idx] = acc;
    }
}

// ---------------------------------------------------------------------------
// Dynamic smem request 118 KB: 2 x 118KB > 228 KB carveout -> exactly ONE CTA
// per SM. Producers (bids 0..31, wave-1 deterministic placement) own their
// SMs for the whole run; consumers cycle through the remaining 116 SMs.
// Consumer layout (floats):
//   [0, 8192)      sWo0  (also sc2 coeff buffer during generation)
//   [8192, 24576)  sW double buffer  2 x (64 x 128)
//   [24576, 28672) sS double buffer  2 x (64 x 32)
// Producer RecSmem (~42 KB) overlays the same region.
// ---------------------------------------------------------------------------
#define FUSED_SMEM 120832

struct RecSmem {
    float sU[2][SS * RR];
    float sx[2][DD];
    float sstate[STATE];
    float sP[RR], sP0[RR], sstats[SS], srecur[RR];
    float sredA[256], sredB[256];
    float sc[FF], sph2[FF], sbr[RR], sbs[SS];
};

// ---------------------------------------------------------------------------
// Role 1: recurrence producer (checkpoints + publishes every CHK steps)
// ---------------------------------------------------------------------------
__device__ void recurrence_body(char* smraw,
                                const float* __restrict__ x,
                                const float* __restrict__ Ws,
                                const float* __restrict__ bs,
                                const float* __restrict__ br,
                                const float* __restrict__ Wr,
                                const float* __restrict__ phases) {
    RecSmem* sm = (RecSmem*)smraw;
    const int tid  = threadIdx.x;
    const int lane = tid & 63;
    const int grp  = tid >> 6;
    const int b    = blockIdx.x;

    float wsr[48];
#pragma unroll
    for (int kk = 0; kk < 48; ++kk)
        wsr[kk] = Ws[(grp * 48 + kk) * SS + lane];
    float wr0r[16];
#pragma unroll
    for (int ss = 0; ss < 16; ++ss)
        wr0r[ss] = Wr[(grp * 16 + ss) * RR + lane];

    for (int i = tid; i < STATE; i += 256) sm->sstate[i] = 0.f;
    if (tid < RR) { sm->sP[tid] = 0.f; sm->sP0[tid] = 0.f; sm->sbr[tid] = br[tid]; }
    if (tid < SS) { sm->sbs[tid] = bs[tid]; }
    if (tid < FF) { sm->sph2[tid] = TWO_PI * phases[tid]; }

    {
        const float* Usrc = g_U;
#pragma unroll
        for (int q = 0; q < 4; ++q) {
            int i = tid + q * 256;
            __pipeline_memcpy_async(&sm->sU[0][i * 4], &Usrc[i * 4], 16);
        }
        if (tid < 32)
            __pipeline_memcpy_async(&sm->sx[0][tid * 4],
                                    x + ((size_t)b * TT) * DD + tid * 4, 16);
        __pipeline_commit();
    }

    const float invL  = 1.0f / (float)TT;
    const float wbase = TWO_PI / (float)TT;

    for (int t = 1; t <= TT; ++t) {
        const int cur = (t - 1) & 1;
        const int nxt = cur ^ 1;

        __pipeline_wait_prior(0);
        __syncthreads();

        if (t < TT) {
            const float* Usrc = g_U + (size_t)t * (SS * RR);
#pragma unroll
            for (int q = 0; q < 4; ++q) {
                int i = tid + q * 256;
                __pipeline_memcpy_async(&sm->sU[nxt][i * 4], &Usrc[i * 4], 16);
            }
            if (tid < 32)
                __pipeline_memcpy_async(&sm->sx[nxt][tid * 4],
                                        x + ((size_t)b * TT + t) * DD + tid * 4, 16);
            __pipeline_commit();
        }

        if (tid < FF) {
            float fv = (float)tid;
            sm->sc[tid] = invL * cosf(wbase * (float)t * fv + sm->sph2[tid]);
        }
        if (tid < RR) {
            float v = sm->sP[tid] + sm->sbr[tid];
            sm->srecur[tid] = gelu_exact(v);
        }
        __syncthreads();

        {
            float a0 = 0.f, a1 = 0.f, a2 = 0.f, a3 = 0.f;
            const int k0 = grp * 48;
#pragma unroll
            for (int kk = 0; kk < 48; ++kk) {
                int k = k0 + kk;
                float v = (k < DD) ? sm->sx[cur][k] : sm->srecur[k - DD];
                float p = v * wsr[kk];
                if ((kk & 3) == 0) a0 += p;
                else if ((kk & 3) == 1) a1 += p;
                else if ((kk & 3) == 2) a2 += p;
                else a3 += p;
            }
            sm->sredA[grp * 64 + lane] = (a0 + a1) + (a2 + a3);
        }
        __syncthreads();

        if (tid < SS) {
            float v = sm->sredA[tid] + sm->sredA[64 + tid] + sm->sredA[128 + tid] +
                      sm->sredA[192 + tid] + sm->sbs[tid];
            float g = gelu_exact(v);
            sm->sstats[tid] = g;
            g_stats[(size_t)t * (SS * BB) + tid * BB + b] = g;   // [t][s][b]
        }
        __syncthreads();

        {
#pragma unroll
            for (int q = 0; q < 4; ++q) {
                int i = tid + q * 256;
                int f = i >> 6, s = i & 63;
                float prev = (f == 0) ? 0.f : sm->sstate[i];
                float ns = prev + sm->sc[f] * sm->sstats[s];
                sm->sstate[i] = ns;
                if ((t & (CHK - 1)) == 0)
                    g_chk[(size_t)(t / CHK) * (STATE * BB) + i * BB + b] = ns;
            }
        }

        {
            float a1 = 0.f, b1 = 0.f, a2 = 0.f, b2 = 0.f;
            const int s0 = grp * 16;
#pragma unroll
            for (int ss = 0; ss < 16; ++ss) {
                float sv = sm->sstats[s0 + ss];
                float u  = sm->sU[cur][(s0 + ss) * RR + lane];
                if (ss & 1) { a1 += sv * u; b1 += sv * wr0r[ss]; }
                else        { a2 += sv * u; b2 += sv * wr0r[ss]; }
            }
            sm->sredA[grp * 64 + lane] = a1 + a2;
            sm->sredB[grp * 64 + lane] = b1 + b2;
        }
        __syncthreads();

        if (tid < RR) {
            float su = sm->sredA[tid] + sm->sredA[64 + tid] + sm->sredA[128 + tid] + sm->sredA[192 + tid];
            float sw = sm->sredB[tid] + sm->sredB[64 + tid] + sm->sredB[128 + tid] + sm->sredB[192 + tid];
            float np = sm->sP[tid] - sm->sP0[tid] + su;
            sm->sP[tid]  = np;
            sm->sP0[tid] = sm->sc[0] * sw;
        }
        if ((t & (CHK - 1)) == 0 && tid == 128) {
            __threadfence();
            atomicAdd(&g_done[t / CHK], 1);
        }
    }
}

// ---------------------------------------------------------------------------
// Role 2: consumer. CTA = (chunk c, jtile j0 of 128).
//   Phase 1 (no wait): generate M_t slice into g_W (register-cached Wo rows).
//   Phase 2 (wait g_done[c]): rebuild G from checkpoint (rows 64..1023).
//   Phase 3 (wait g_done[c+1]): 32 incremental steps, write output.
// Thread tile 4b x 4j; warp = 4 jg x 8 bg (broadcast-friendly).
// ---------------------------------------------------------------------------
__device__ void consumer_body(char* smraw,
                              const float* __restrict__ Wo,
                              const float* __restrict__ bo,
                              float* __restrict__ out) {
    float* sWo0 = (float*)smraw;              // 8192 floats (also sc2)
    float* sW   = (float*)smraw + 8192;       // 2 x 8192
    float* sS   = (float*)smraw + 24576;      // 2 x 2048

    const int tid = threadIdx.x;
    const int ci  = (int)blockIdx.x - BB;
    const int c   = ci >> 3;                  // chunk 0..63
    const int j0  = (ci & 7) * JT;            // 0..896
    const int jg  = tid >> 3;                 // 0..31
    const int bg  = tid & 7;                  // 0..7
    const int jj  = jg * 4;
    const int b4  = bg * 4;

    // ---------------- Phase 1: generate M slice (no dependency) ------------
    {
        float* sc2 = sWo0;                    // overlay
        for (int i = tid; i < CHK * FF; i += 256)
            sc2[i] = g_C[(c * CHK + 1) * FF + i];
        __syncthreads();
        float* wslice = g_W + (size_t)ci * (CHK * SS * JT);
        for (int q = 0; q < 32; ++q) {
            int p = q * 256 + tid;            // 0..8191 : s = p>>7, j = p&127
            int s = p >> 7, j = p & 127;
            float wo[FF - 1];
#pragma unroll
            for (int f = 0; f < FF - 1; ++f)
                wo[f] = Wo[(size_t)((f + 1) * SS + s) * STATE + j0 + j];
#pragma unroll 4
            for (int tt = 0; tt < CHK; ++tt) {
                float acc = 0.f;
#pragma unroll
                for (int f = 0; f < FF - 1; ++f)
                    acc += sc2[tt * FF + f + 1] * wo[f];
                wslice[(size_t)tt * (SS * JT) + p] = acc;
            }
        }
        __syncthreads();                      // done with sc2 overlay
    }

    // Stage Wo0 (rows 0..63) into sWo0
    for (int q = 0; q < 8; ++q) {
        int i = q * 256 + tid;                // 16B units, 0..2047
        int k = i >> 5, seg = i & 31;
        __pipeline_memcpy_async(sWo0 + i * 4,
                                Wo + (size_t)k * STATE + j0 + seg * 4, 16);
    }
    __pipeline_commit();

    const float bo0 = bo[j0 + jj], bo1 = bo[j0 + jj + 1];
    const float bo2 = bo[j0 + jj + 2], bo3 = bo[j0 + jj + 3];

    float G[16];
#pragma unroll
    for (int i = 0; i < 16; ++i) G[i] = 0.f;

    // ---------------- Phase 2: rebuild from checkpoint ---------------------
    if (c > 0) {
        if (tid == 0) {
            while (*(volatile int*)&g_done[c] < BB) __nanosleep(512);
            __threadfence();
        }
        __syncthreads();
        const float* chkp = g_chk + (size_t)c * (STATE * BB);
#define PF_R(kt, buf) do {                                                     \
    for (int q = 0; q < 8; ++q) {                                              \
        int i = q * 256 + tid;                                                 \
        int k = i >> 5, seg = i & 31;                                          \
        __pipeline_memcpy_async(sW + (buf) * 8192 + i * 4,                     \
            Wo + (size_t)((kt) * 64 + k) * STATE + j0 + seg * 4, 16);          \
    }                                                                          \
    for (int q = 0; q < 2; ++q) {                                              \
        int i = q * 256 + tid;                                                 \
        __pipeline_memcpy_async(sS + (buf) * 2048 + i * 4,                     \
            chkp + (size_t)(kt) * 64 * BB + i * 4, 16);                        \
    }                                                                          \
    __pipeline_commit();                                                       \
} while (0)
        PF_R(1, 0);
        for (int kt = 1; kt < 16; ++kt) {
            const int buf = (kt - 1) & 1;
            __pipeline_wait_prior(0);
            __syncthreads();
            if (kt < 15) PF_R(kt + 1, buf ^ 1);
            const float* ws = sW + buf * 8192;
            const float* cs = sS + buf * 2048;
#pragma unroll 8
            for (int k = 0; k < 64; ++k) {
                float4 sv = *(const float4*)&cs[k * 32 + b4];
                float4 wv = *(const float4*)&ws[k * 128 + jj];
                G[0]  += sv.x * wv.x; G[1]  += sv.x * wv.y; G[2]  += sv.x * wv.z; G[3]  += sv.x * wv.w;
                G[4]  += sv.y * wv.x; G[5]  += sv.y * wv.y; G[6]  += sv.y * wv.z; G[7]  += sv.y * wv.w;
                G[8]  += sv.z * wv.x; G[9]  += sv.z * wv.y; G[10] += sv.z * wv.z; G[11] += sv.z * wv.w;
                G[12] += sv.w * wv.x; G[13] += sv.w * wv.y; G[14] += sv.w * wv.z; G[15] += sv.w * wv.w;
            }
            __syncthreads();
        }
#undef PF_R
    }

    // ---------------- Phase 3: incremental 32 steps -------------------------
    if (tid == 0) {
        while (*(volatile int*)&g_done[c + 1] < BB) __nanosleep(512);
        __threadfence();
    }
    __syncthreads();

    const float* wslice = g_W + (size_t)ci * (CHK * SS * JT);
#define PF_M(tt, buf) do {                                                     \
    for (int q = 0; q < 8; ++q) {                                              \
        int i = q * 256 + tid;                                                 \
        __pipeline_memcpy_async(sW + (buf) * 8192 + i * 4,                     \
            wslice + (size_t)(tt) * (SS * JT) + i * 4, 16);                    \
    }                                                                          \
    for (int q = 0; q < 2; ++q) {                                              \
        int i = q * 256 + tid;                                                 \
        __pipeline_memcpy_async(sS + (buf) * 2048 + i * 4,                     \
            g_stats + (size_t)(c * CHK + 1 + (tt)) * (SS * BB) + i * 4, 16);   \
    }                                                                          \
    __pipeline_commit();                                                       \
} while (0)

    PF_M(0, 0);
    for (int tt = 0; tt < CHK; ++tt) {
        const int t = c * CHK + 1 + tt;
        const int buf = tt & 1;
        __pipeline_wait_prior(0);
        __syncthreads();
        if (tt < CHK - 1) PF_M(tt + 1, buf ^ 1);

        const float* ws = sW + buf * 8192;
        const float* cs = sS + buf * 2048;
        float v[16], qc[16];
#pragma unroll
        for (int i = 0; i < 16; ++i) { v[i] = 0.f; qc[i] = 0.f; }
#pragma unroll 8
        for (int k = 0; k < 64; ++k) {
            float4 sv = *(const float4*)&cs[k * 32 + b4];
            float4 wv = *(const float4*)&ws[k * 128 + jj];
            float4 w0 = *(const float4*)&sWo0[k * 128 + jj];
            v[0]  += sv.x * wv.x; v[1]  += sv.x * wv.y; v[2]  += sv.x * wv.z; v[3]  += sv.x * wv.w;
            v[4]  += sv.y * wv.x; v[5]  += sv.y * wv.y; v[6]  += sv.y * wv.z; v[7]  += sv.y * wv.w;
            v[8]  += sv.z * wv.x; v[9]  += sv.z * wv.y; v[10] += sv.z * wv.z; v[11] += sv.z * wv.w;
            v[12] += sv.w * wv.x; v[13] += sv.w * wv.y; v[14] += sv.w * wv.z; v[15] += sv.w * wv.w;
            qc[0]  += sv.x * w0.x; qc[1]  += sv.x * w0.y; qc[2]  += sv.x * w0.z; qc[3]  += sv.x * w0.w;
            qc[4]  += sv.y * w0.x; qc[5]  += sv.y * w0.y; qc[6]  += sv.y * w0.z; qc[7]  += sv.y * w0.w;
            qc[8]  += sv.z * w0.x; qc[9]  += sv.z * w0.y; qc[10] += sv.z * w0.z; qc[11] += sv.z * w0.w;
            qc[12] += sv.w * w0.x; qc[13] += sv.w * w0.y; qc[14] += sv.w * w0.z; qc[15] += sv.w * w0.w;
        }
        const float c0 = __ldg(&g_C[t * FF]);
#pragma unroll
        for (int i = 0; i < 16; ++i) G[i] += v[i];
#pragma unroll
        for (int i = 0; i < 4; ++i) {
            float4 o;
            o.x = gelu_exact(G[i * 4 + 0] + c0 * qc[i * 4 + 0] + bo0);
            o.y = gelu_exact(G[i * 4 + 1] + c0 * qc[i * 4 + 1] + bo1);
            o.z = gelu_exact(G[i * 4 + 2] + c0 * qc[i * 4 + 2] + bo2);
            o.w = gelu_exact(G[i * 4 + 3] + c0 * qc[i * 4 + 3] + bo3);
            *(float4*)(out + ((size_t)(b4 + i) * TT + (t - 1)) * STATE + j0 + jj) = o;
        }
    }
#undef PF_M
}

// ---------------------------------------------------------------------------
__global__ __launch_bounds__(256, 1)
void fru_fused(const float* __restrict__ x,
               const float* __restrict__ Ws,
               const float* __restrict__ bs,
               const float* __restrict__ br,
               const float* __restrict__ Wr,
               const float* __restrict__ phases,
               const float* __restrict__ Wo,
               const float* __restrict__ bo,
               float* __restrict__ out) {
    extern __shared__ __align__(128) char smraw[];
    if (blockIdx.x < BB)
        recurrence_body(smraw, x, Ws, bs, br, Wr, phases);
    else
        consumer_body(smraw, Wo, bo, out);
}

// ---------------------------------------------------------------------------
extern "C" void kernel_launch(void* const* d_in, const int* in_sizes, int n_in,
                              void* d_out, int out_size) {
    const float* x   = (const float*)d_in[0];  // (B,T,D)
    const float* Wr  = (const float*)d_in[1];  // (STATE,R)
    const float* br  = (const float*)d_in[2];  // (R,)
    const float* Ws  = (const float*)d_in[3];  // (D+R,S)
    const float* bs  = (const float*)d_in[4];  // (S,)
    const float* Wo  = (const float*)d_in[5];  // (STATE,STATE)
    const float* bo  = (const float*)d_in[6];  // (STATE,)
    const float* ph  = (const float*)d_in[7];  // (1,F,1)
    float* out = (float*)d_out;

    cudaFuncSetAttribute(fru_fused, cudaFuncAttributeMaxDynamicSharedMemorySize, FUSED_SMEM);

    precompute_U<<<TT, 256>>>(Wr, ph);
    fru_fused<<<BB + NCONS, 256, FUSED_SMEM>>>(x, Ws, bs, br, Wr, ph, Wo, bo, out);
}